// round 1
// baseline (speedup 1.0000x reference)
#include <cuda_runtime.h>
#include <cuda_bf16.h>

// SAN pairwise subtraction: out[n,c,kk,oh*ow] = x[n,c,oh,ow] - xpad[n,c,oh+i,ow+j]
// k=7, s=1, p=3, d=1, H=W=56 -> out_h=out_w=56.
// Input 3.2 MB, output 314.7 MB -> pure HBM-write-bound expansion.
//
// Strategy: one CTA per (n,c) plane. Stage the 12.5KB plane into a zero-padded
// 62x64 smem tile (stride 64 keeps float4 reads aligned + conflict-free).
// Each thread owns a 4-column group (oh, ow4) and loops i=0..6 rows: 3 aligned
// LDS.128 cover the 10-float sliding window, register-windowed into 7 output
// float4s (one per j). 21 LDS.128 per 49 STG.128 -> smem cost negligible,
// stores fully coalesced along the contiguous inner dim.

#define SAN_H 56
#define SAN_W 56
#define SSTRIDE 64          // padded smem row stride (floats)
#define PROWS 62            // 56 + 2*3 padded rows
#define PLANE_OUT (49 * 3136)

__global__ __launch_bounds__(256) void san_sub_kernel(const float* __restrict__ x,
                                                      float* __restrict__ out) {
    __shared__ float s[PROWS * SSTRIDE];
    const int plane = blockIdx.x;          // n*64 + c, 0..511
    const int tid = threadIdx.x;

    // Zero-fill padded tile (borders must be 0)
    #pragma unroll
    for (int i = tid; i < PROWS * SSTRIDE; i += 256) s[i] = 0.0f;
    __syncthreads();

    // Load plane into padded interior
    const float* xp = x + (size_t)plane * (SAN_H * SAN_W);
    for (int i = tid; i < SAN_H * SAN_W; i += 256) {
        int r = i / SAN_W;
        int c = i - r * SAN_W;
        s[(r + 3) * SSTRIDE + (c + 3)] = xp[i];
    }
    __syncthreads();

    float* op = out + (size_t)plane * PLANE_OUT;

    // 784 float4 positions per (kk) slice: oh in [0,56), ow4 in {0,4,...,52}
    for (int pos = tid; pos < 784; pos += 256) {
        int oh = pos / 14;
        int ow4 = (pos - oh * 14) * 4;

        // center = xpad[oh+3, ow+3] for ow = ow4..ow4+3
        const float* crow = &s[(oh + 3) * SSTRIDE + ow4 + 3];
        float c0 = crow[0];
        float c1 = crow[1];
        float c2 = crow[2];
        float c3 = crow[3];

        #pragma unroll
        for (int i = 0; i < 7; i++) {
            const float4* row =
                reinterpret_cast<const float4*>(&s[(oh + i) * SSTRIDE + ow4]);
            float4 a = row[0];
            float4 b = row[1];
            float4 cc = row[2];  // cols ow4+8..11; 62/63 are zeroed stride pad
            float r[12] = {a.x, a.y, a.z, a.w,
                           b.x, b.y, b.z, b.w,
                           cc.x, cc.y, cc.z, cc.w};
            #pragma unroll
            for (int j = 0; j < 7; j++) {
                float4 o;
                o.x = c0 - r[j + 0];
                o.y = c1 - r[j + 1];
                o.z = c2 - r[j + 2];
                o.w = c3 - r[j + 3];
                reinterpret_cast<float4*>(op)[(i * 7 + j) * 784 + pos] = o;
            }
        }
    }
}

extern "C" void kernel_launch(void* const* d_in, const int* in_sizes, int n_in,
                              void* d_out, int out_size) {
    const float* x = (const float*)d_in[0];
    float* out = (float*)d_out;
    // 8 * 64 = 512 planes
    san_sub_kernel<<<512, 256>>>(x, out);
}

// round 2
// speedup vs baseline: 1.3173x; 1.3173x over previous
#include <cuda_runtime.h>
#include <cuda_bf16.h>

// SAN pairwise subtraction: out[n,c,kk,oh*ow] = x[n,c,oh,ow] - xpad[n,c,oh+i,ow+j]
// k=7, s=1, p=3, d=1, H=W=56 -> out_h=out_w=56. Output 314.7 MB -> HBM-write-bound.
//
// R2: split each (n,c) plane into 4 oh-chunks of 14 rows.
// grid = 512 planes * 4 chunks = 2048 CTAs, block = 256.
// Each CTA stages a zero-padded 20x64 smem window (5 KB) and 196 threads each
// own one (oh, ow4) float4 position: per neighbor row i, 3 aligned LDS.128
// cover the 10-float sliding window, register-windowed into 7 STG.128 (one per
// j offset). Streaming stores (__stcs) since output is never re-read.

#define SAN_H 56
#define SAN_W 56
#define SSTRIDE 64          // padded smem row stride (floats)
#define CHUNK 14            // oh rows per CTA
#define PROWS (CHUNK + 6)   // 20 padded rows staged
#define PLANE_OUT (49 * 3136)

__global__ __launch_bounds__(256) void san_sub_kernel(const float* __restrict__ x,
                                                      float* __restrict__ out) {
    __shared__ float s[PROWS * SSTRIDE];
    const int bx = blockIdx.x;
    const int plane = bx >> 2;           // n*64 + c, 0..511
    const int chunk = bx & 3;            // 0..3, oh block of 14 rows
    const int tid = threadIdx.x;
    const int oh0 = chunk * CHUNK;

    // Stage padded window: smem row pr corresponds to padded row oh0+pr,
    // i.e. global row g = oh0 + pr - 3. Zero-fill borders.
    const float* xp = x + (size_t)plane * (SAN_H * SAN_W);
    #pragma unroll
    for (int idx = tid; idx < PROWS * SSTRIDE; idx += 256) {
        int pr = idx >> 6;
        int c = idx & 63;
        int g = oh0 + pr - 3;
        int gc = c - 3;
        float v = 0.0f;
        if ((unsigned)g < SAN_H && (unsigned)gc < SAN_W) v = xp[g * SAN_W + gc];
        s[idx] = v;
    }
    __syncthreads();

    if (tid >= 196) return;

    const int oh_l = tid / 14;           // 0..13 local row
    const int owq = tid - oh_l * 14;     // 0..13 quad-column index
    const int ow4 = owq * 4;
    const int pos = (oh0 + oh_l) * 14 + owq;   // global float4 position 0..783

    float* op = out + (size_t)plane * PLANE_OUT;

    // center = xpad[oh+3, ow+3] -> smem row oh_l+3, cols ow4+3..ow4+6
    const float* crow = &s[(oh_l + 3) * SSTRIDE + ow4 + 3];
    const float c0 = crow[0];
    const float c1 = crow[1];
    const float c2 = crow[2];
    const float c3 = crow[3];

    #pragma unroll
    for (int i = 0; i < 7; i++) {
        const float4* row =
            reinterpret_cast<const float4*>(&s[(oh_l + i) * SSTRIDE + ow4]);
        float4 a = row[0];
        float4 b = row[1];
        float4 cc = row[2];   // cols ow4+8..11 (stride pad cols are zeroed)
        float r[12] = {a.x, a.y, a.z, a.w,
                       b.x, b.y, b.z, b.w,
                       cc.x, cc.y, cc.z, cc.w};
        #pragma unroll
        for (int j = 0; j < 7; j++) {
            float4 o;
            o.x = c0 - r[j + 0];
            o.y = c1 - r[j + 1];
            o.z = c2 - r[j + 2];
            o.w = c3 - r[j + 3];
            __stcs(reinterpret_cast<float4*>(op) + (size_t)(i * 7 + j) * 784 + pos, o);
        }
    }
}

extern "C" void kernel_launch(void* const* d_in, const int* in_sizes, int n_in,
                              void* d_out, int out_size) {
    const float* x = (const float*)d_in[0];
    float* out = (float*)d_out;
    // 512 planes * 4 oh-chunks
    san_sub_kernel<<<2048, 256>>>(x, out);
}

// round 3
// speedup vs baseline: 1.3181x; 1.0006x over previous
#include <cuda_runtime.h>
#include <cuda_bf16.h>

// SAN pairwise subtraction: out[n,c,kk,oh*ow] = x[n,c,oh,ow] - xpad[n,c,oh+i,ow+j]
// k=7, s=1, p=3, d=1, H=W=56 -> out_h=out_w=56. Output 314.7 MB -> HBM-write-bound.
//
// R3: CHUNK=8 rows per CTA, block=128 (112 store-owning threads = 3.5/4 warps
// active, vs 6.125/8 in R2), grid = 512 planes * 7 chunks = 3584. Regs ~44 ->
// 11 CTAs/SM resident: ~38.5 effective store-issuing warps per SM (+26% vs R2).
// Inner loop unchanged: stage zero-padded 14x64 smem window (3.5 KB); per
// neighbor row i, 3 aligned LDS.128 cover the 10-float sliding window,
// register-windowed into 7 streaming STG.128 (one per j offset).

#define SAN_H 56
#define SAN_W 56
#define SSTRIDE 64          // padded smem row stride (floats)
#define CHUNK 8             // oh rows per CTA
#define PROWS (CHUNK + 6)   // 14 padded rows staged
#define PLANE_OUT (49 * 3136)

__global__ __launch_bounds__(128) void san_sub_kernel(const float* __restrict__ x,
                                                      float* __restrict__ out) {
    __shared__ float s[PROWS * SSTRIDE];
    const int bx = blockIdx.x;
    const int plane = bx / 7;            // n*64 + c, 0..511
    const int chunk = bx - plane * 7;    // 0..6, oh block of 8 rows
    const int tid = threadIdx.x;
    const int oh0 = chunk * CHUNK;

    // Stage padded window: smem row pr = padded row oh0+pr, global row
    // g = oh0 + pr - 3. Zero-fill borders. 14*64/128 = 7 iterations exactly.
    const float* xp = x + (size_t)plane * (SAN_H * SAN_W);
    #pragma unroll
    for (int it = 0; it < 7; it++) {
        int idx = it * 128 + tid;
        int pr = idx >> 6;
        int c = idx & 63;
        int g = oh0 + pr - 3;
        int gc = c - 3;
        float v = 0.0f;
        if ((unsigned)g < SAN_H && (unsigned)gc < SAN_W) v = xp[g * SAN_W + gc];
        s[idx] = v;
    }
    __syncthreads();

    if (tid >= CHUNK * 14) return;       // 112 active threads

    const int oh_l = tid / 14;           // 0..7 local row
    const int owq = tid - oh_l * 14;     // 0..13 quad-column index
    const int ow4 = owq * 4;
    const int pos = (oh0 + oh_l) * 14 + owq;   // global float4 position 0..783

    float* op = out + (size_t)plane * PLANE_OUT;

    // center = xpad[oh+3, ow+3] -> smem row oh_l+3, cols ow4+3..ow4+6
    const float* crow = &s[(oh_l + 3) * SSTRIDE + ow4 + 3];
    const float c0 = crow[0];
    const float c1 = crow[1];
    const float c2 = crow[2];
    const float c3 = crow[3];

    #pragma unroll
    for (int i = 0; i < 7; i++) {
        const float4* row =
            reinterpret_cast<const float4*>(&s[(oh_l + i) * SSTRIDE + ow4]);
        float4 a = row[0];
        float4 b = row[1];
        float4 cc = row[2];   // cols ow4+8..11 (stride pad cols are zeroed)
        float r[12] = {a.x, a.y, a.z, a.w,
                       b.x, b.y, b.z, b.w,
                       cc.x, cc.y, cc.z, cc.w};
        #pragma unroll
        for (int j = 0; j < 7; j++) {
            float4 o;
            o.x = c0 - r[j + 0];
            o.y = c1 - r[j + 1];
            o.z = c2 - r[j + 2];
            o.w = c3 - r[j + 3];
            __stcs(reinterpret_cast<float4*>(op) + (size_t)(i * 7 + j) * 784 + pos, o);
        }
    }
}

extern "C" void kernel_launch(void* const* d_in, const int* in_sizes, int n_in,
                              void* d_out, int out_size) {
    const float* x = (const float*)d_in[0];
    float* out = (float*)d_out;
    // 512 planes * 7 oh-chunks of 8 rows
    san_sub_kernel<<<3584, 128>>>(x, out);
}